// round 5
// baseline (speedup 1.0000x reference)
#include <cuda_runtime.h>

// NNUE forward, fully fused: one CTA per batch row.
// Pipeline per row:
//   1. gather-accumulate 2x32 rows of W_ft (float4 per thread, coalesced)
//   2. us/them perspective combine + clamp [0,1]
//   3. pairwise products (s0*s1, s2*s3) * 127/128 -> l0p[1024] in SMEM
//   4. L1: 16 dots of 1024 (register partials -> shuffle -> SMEM reduce)
//   5. L2/L3 tail on one warp
//
// Inputs (metadata order):
//  0 us(B) 1 them(B) 2 white_indices(B*32 i32) 3 white_values(B*32)
//  4 black_indices 5 black_values 6 layer_stack_indices(B i32)
//  7 W_ft(22528*1024) 8 b_ft(1024) 9 W1(1024*144) 10 b1(144)
// 11 W2(30*288) 12 b2(288) 13 W3(32*9) 14 b3(9)

#define KIDX   32
#define L1DIM  1024
#define L2DIM  15
#define L3DIM  32
#define NBUCK  9
#define W1COLS (NBUCK * (L2DIM + 1))   // 144
#define W2COLS (NBUCK * L3DIM)         // 288
#define FSC    (127.0f / 128.0f)

static __device__ __forceinline__ float clamp01(float x) {
    return fminf(fmaxf(x, 0.0f), 1.0f);
}

__global__ __launch_bounds__(256, 4)
void nnue_fused_kernel(
    const float* __restrict__ us,   const float* __restrict__ them,
    const int*   __restrict__ widx, const float* __restrict__ wval,
    const int*   __restrict__ bidx, const float* __restrict__ bval,
    const int*   __restrict__ lsi,
    const float* __restrict__ W_ft, const float* __restrict__ b_ft,
    const float* __restrict__ W1,   const float* __restrict__ b1,
    const float* __restrict__ W2,   const float* __restrict__ b2,
    const float* __restrict__ W3,   const float* __restrict__ b3,
    float* __restrict__ out)
{
    const int b = blockIdx.x;
    const int t = threadIdx.x;          // 0..255, owns columns 4t..4t+3
    const int warp = t >> 5;
    const int lane = t & 31;

    __shared__ int   s_idx[2 * KIDX];
    __shared__ float s_val[2 * KIDX];
    __shared__ float s_a[L1DIM];        // l0 first half  (clamped)
    __shared__ float s_b[L1DIM];        // l0 second half (clamped)
    __shared__ float s_l0p[L1DIM];      // pairwise-product activation
    __shared__ float s_part[16 * 8];    // per-warp L1 partials
    __shared__ float s_l1[16];          // l1c bucket slice

    // ---- stage 0: indices/values into SMEM (broadcast to all threads) ----
    if (t < KIDX) {
        s_idx[t] = widx[b * KIDX + t];
        s_val[t] = wval[b * KIDX + t];
    } else if (t < 2 * KIDX) {
        s_idx[t] = bidx[b * KIDX + (t - KIDX)];
        s_val[t] = bval[b * KIDX + (t - KIDX)];
    }
    __syncthreads();

    // ---- stage 1: feature-transform gather/accumulate ----
    const float4* bft4 = reinterpret_cast<const float4*>(b_ft);
    float4 wp = bft4[t];
    float4 bp = wp;

    #pragma unroll 8
    for (int k = 0; k < KIDX; k++) {
        const float4* row = reinterpret_cast<const float4*>(
            W_ft + (size_t)s_idx[k] * L1DIM);
        const float  v = s_val[k];
        const float4 r = row[t];
        wp.x = fmaf(v, r.x, wp.x); wp.y = fmaf(v, r.y, wp.y);
        wp.z = fmaf(v, r.z, wp.z); wp.w = fmaf(v, r.w, wp.w);
    }
    #pragma unroll 8
    for (int k = KIDX; k < 2 * KIDX; k++) {
        const float4* row = reinterpret_cast<const float4*>(
            W_ft + (size_t)s_idx[k] * L1DIM);
        const float  v = s_val[k];
        const float4 r = row[t];
        bp.x = fmaf(v, r.x, bp.x); bp.y = fmaf(v, r.y, bp.y);
        bp.z = fmaf(v, r.z, bp.z); bp.w = fmaf(v, r.w, bp.w);
    }

    // ---- stage 2: perspective combine + clamp ----
    const float u  = us[b];
    const float th = them[b];
    float4 a, c;
    a.x = clamp01(u * wp.x + th * bp.x);  c.x = clamp01(u * bp.x + th * wp.x);
    a.y = clamp01(u * wp.y + th * bp.y);  c.y = clamp01(u * bp.y + th * wp.y);
    a.z = clamp01(u * wp.z + th * bp.z);  c.z = clamp01(u * bp.z + th * wp.z);
    a.w = clamp01(u * wp.w + th * bp.w);  c.w = clamp01(u * bp.w + th * wp.w);
    reinterpret_cast<float4*>(s_a)[t] = a;
    reinterpret_cast<float4*>(s_b)[t] = c;
    __syncthreads();

    // ---- stage 3: pairwise products: l0p[c]=a[c]*a[c+512], l0p[c+512]=b[c]*b[c+512]
    #pragma unroll
    for (int cix = t; cix < 512; cix += 256) {
        s_l0p[cix]       = s_a[cix] * s_a[cix + 512] * FSC;
        s_l0p[cix + 512] = s_b[cix] * s_b[cix + 512] * FSC;
    }
    __syncthreads();

    // ---- stage 4: L1 — 16 dots of 1024 over the selected bucket ----
    const int bucket = lsi[b];
    float p[16];
    #pragma unroll
    for (int j = 0; j < 16; j++) p[j] = 0.0f;

    const float* w1b = W1 + bucket * (L2DIM + 1) * 1;  // + bucket*16 columns
    // (column offset inside each 144-wide row)
    #pragma unroll
    for (int e4 = 0; e4 < 4; e4++) {
        const int   e = 4 * t + e4;
        const float x = s_l0p[e];
        const float4* wr = reinterpret_cast<const float4*>(
            W1 + (size_t)e * W1COLS + bucket * 16);
        const float4 q0 = wr[0], q1 = wr[1], q2 = wr[2], q3 = wr[3];
        p[0]  = fmaf(x, q0.x, p[0]);  p[1]  = fmaf(x, q0.y, p[1]);
        p[2]  = fmaf(x, q0.z, p[2]);  p[3]  = fmaf(x, q0.w, p[3]);
        p[4]  = fmaf(x, q1.x, p[4]);  p[5]  = fmaf(x, q1.y, p[5]);
        p[6]  = fmaf(x, q1.z, p[6]);  p[7]  = fmaf(x, q1.w, p[7]);
        p[8]  = fmaf(x, q2.x, p[8]);  p[9]  = fmaf(x, q2.y, p[9]);
        p[10] = fmaf(x, q2.z, p[10]); p[11] = fmaf(x, q2.w, p[11]);
        p[12] = fmaf(x, q3.x, p[12]); p[13] = fmaf(x, q3.y, p[13]);
        p[14] = fmaf(x, q3.z, p[14]); p[15] = fmaf(x, q3.w, p[15]);
    }
    (void)w1b;

    // warp tree-reduce each of the 16 partials
    #pragma unroll
    for (int j = 0; j < 16; j++) {
        #pragma unroll
        for (int o = 16; o > 0; o >>= 1)
            p[j] += __shfl_xor_sync(0xffffffffu, p[j], o);
    }
    if (lane == 0) {
        #pragma unroll
        for (int j = 0; j < 16; j++) s_part[j * 8 + warp] = p[j];
    }
    __syncthreads();

    if (t < 16) {
        float s = b1[bucket * 16 + t];
        #pragma unroll
        for (int w = 0; w < 8; w++) s += s_part[t * 8 + w];
        s_l1[t] = s;
    }
    __syncthreads();

    // ---- stage 5: L2 + L3 tail on warp 0 ----
    if (t < 32) {
        const float l1f = s_l1[15];          // pass-through term, NOT clipped
        float acc = b2[bucket * L3DIM + t];
        #pragma unroll
        for (int i = 0; i < L2DIM; i++) {
            const float x  = clamp01(s_l1[i]);
            const float wa = W2[(size_t)i * W2COLS + bucket * L3DIM + t];         // x^2 term
            const float wb = W2[(size_t)(i + L2DIM) * W2COLS + bucket * L3DIM + t]; // linear term
            acc = fmaf(x * x * FSC, wa, acc);
            acc = fmaf(x * FSC,     wb, acc);
        }
        const float l2x = clamp01(acc);
        float contrib = l2x * W3[t * NBUCK + bucket];
        #pragma unroll
        for (int o = 16; o > 0; o >>= 1)
            contrib += __shfl_xor_sync(0xffffffffu, contrib, o);
        if (t == 0) out[b] = contrib + b3[bucket] + l1f;
    }
}

extern "C" void kernel_launch(void* const* d_in, const int* in_sizes, int n_in,
                              void* d_out, int out_size) {
    const float* us   = (const float*)d_in[0];
    const float* them = (const float*)d_in[1];
    const int*   widx = (const int*)  d_in[2];
    const float* wval = (const float*)d_in[3];
    const int*   bidx = (const int*)  d_in[4];
    const float* bval = (const float*)d_in[5];
    const int*   lsi  = (const int*)  d_in[6];
    const float* W_ft = (const float*)d_in[7];
    const float* b_ft = (const float*)d_in[8];
    const float* W1   = (const float*)d_in[9];
    const float* b1   = (const float*)d_in[10];
    const float* W2   = (const float*)d_in[11];
    const float* b2   = (const float*)d_in[12];
    const float* W3   = (const float*)d_in[13];
    const float* b3   = (const float*)d_in[14];
    float* out = (float*)d_out;

    const int B = in_sizes[0];  // us has B elements
    nnue_fused_kernel<<<B, 256>>>(us, them, widx, wval, bidx, bval, lsi,
                                  W_ft, b_ft, W1, b1, W2, b2, W3, b3, out);
}

// round 6
// speedup vs baseline: 1.4425x; 1.4425x over previous
#include <cuda_runtime.h>
#include <cuda_fp16.h>

// NNUE forward, fused. v2:
//  - prologue A: W_ft fp32 -> fp16 into __device__ scratch (halves gather traffic)
//  - prologue B: W1 transposed to [bucket][j][e] (coalesced L1-layer loads)
//  - main: one CTA per batch row
//
// Inputs (metadata order):
//  0 us(B) 1 them(B) 2 white_indices(B*32 i32) 3 white_values(B*32)
//  4 black_indices 5 black_values 6 layer_stack_indices(B i32)
//  7 W_ft(22528*1024) 8 b_ft(1024) 9 W1(1024*144) 10 b1(144)
// 11 W2(30*288) 12 b2(288) 13 W3(32*9) 14 b3(9)

#define KIDX   32
#define L1DIM  1024
#define L2DIM  15
#define L3DIM  32
#define NBUCK  9
#define NF     22528
#define W1COLS (NBUCK * (L2DIM + 1))   // 144
#define W2COLS (NBUCK * L3DIM)         // 288
#define FSC    (127.0f / 128.0f)

struct __align__(8) Half4 { __half2 a, b; };

__device__ Half4 g_Wft16[(size_t)NF * L1DIM / 4];      // 46 MB fp16 copy of W_ft
__device__ float g_W1t[NBUCK * 16 * L1DIM];            // 576 KB: [bucket][j][e]

static __device__ __forceinline__ float clamp01(float x) {
    return fminf(fmaxf(x, 0.0f), 1.0f);
}

// ---------------- prologue A: fp32 -> fp16 convert ----------------
__global__ __launch_bounds__(256)
void convert_wft_kernel(const float* __restrict__ W_ft) {
    const size_t n4 = (size_t)NF * L1DIM / 4;
    const float4* src = reinterpret_cast<const float4*>(W_ft);
    size_t i = (size_t)blockIdx.x * blockDim.x + threadIdx.x;
    const size_t stride = (size_t)gridDim.x * blockDim.x;
    for (; i < n4; i += stride) {
        float4 v = src[i];
        Half4 h;
        h.a = __floats2half2_rn(v.x, v.y);
        h.b = __floats2half2_rn(v.z, v.w);
        g_Wft16[i] = h;
    }
}

// ---------------- prologue B: W1 transpose ----------------
__global__ __launch_bounds__(256)
void transpose_w1_kernel(const float* __restrict__ W1) {
    const int n = NBUCK * 16 * L1DIM;
    int i = blockIdx.x * blockDim.x + threadIdx.x;
    if (i < n) {
        const int e   = i & (L1DIM - 1);
        const int j   = (i >> 10) & 15;
        const int bkt = i >> 14;
        g_W1t[i] = W1[(size_t)e * W1COLS + bkt * 16 + j];
    }
}

// ---------------- main fused kernel ----------------
__global__ __launch_bounds__(256, 4)
void nnue_fused_kernel(
    const float* __restrict__ us,   const float* __restrict__ them,
    const int*   __restrict__ widx, const float* __restrict__ wval,
    const int*   __restrict__ bidx, const float* __restrict__ bval,
    const int*   __restrict__ lsi,
    const float* __restrict__ b_ft,
    const float* __restrict__ b1,
    const float* __restrict__ W2,   const float* __restrict__ b2,
    const float* __restrict__ W3,   const float* __restrict__ b3,
    float* __restrict__ out)
{
    const int b = blockIdx.x;
    const int t = threadIdx.x;          // 0..255, owns columns 4t..4t+3
    const int warp = t >> 5;
    const int lane = t & 31;

    __shared__ int   s_idx[2 * KIDX];
    __shared__ float s_val[2 * KIDX];
    __shared__ float s_a[L1DIM];        // l0 first half  (clamped)
    __shared__ float s_b[L1DIM];        // l0 second half (clamped)
    __shared__ float s_l0p[L1DIM];      // pairwise-product activation
    __shared__ float s_part[16 * 8];    // per-warp L1 partials
    __shared__ float s_l1[16];          // l1c bucket slice

    // ---- stage 0: indices/values into SMEM ----
    if (t < KIDX) {
        s_idx[t] = widx[b * KIDX + t];
        s_val[t] = wval[b * KIDX + t];
    } else if (t < 2 * KIDX) {
        s_idx[t] = bidx[b * KIDX + (t - KIDX)];
        s_val[t] = bval[b * KIDX + (t - KIDX)];
    }
    __syncthreads();

    // ---- stage 1: fp16 feature-transform gather/accumulate (fp32 math) ----
    const float4* bft4 = reinterpret_cast<const float4*>(b_ft);
    float4 wp = bft4[t];
    float4 bp = wp;

    #pragma unroll 8
    for (int k = 0; k < KIDX; k++) {
        const Half4* row = g_Wft16 + (size_t)s_idx[k] * (L1DIM / 4);
        const float  v = s_val[k];
        const Half4  r = row[t];
        const float2 lo = __half22float2(r.a);
        const float2 hi = __half22float2(r.b);
        wp.x = fmaf(v, lo.x, wp.x); wp.y = fmaf(v, lo.y, wp.y);
        wp.z = fmaf(v, hi.x, wp.z); wp.w = fmaf(v, hi.y, wp.w);
    }
    #pragma unroll 8
    for (int k = KIDX; k < 2 * KIDX; k++) {
        const Half4* row = g_Wft16 + (size_t)s_idx[k] * (L1DIM / 4);
        const float  v = s_val[k];
        const Half4  r = row[t];
        const float2 lo = __half22float2(r.a);
        const float2 hi = __half22float2(r.b);
        bp.x = fmaf(v, lo.x, bp.x); bp.y = fmaf(v, lo.y, bp.y);
        bp.z = fmaf(v, hi.x, bp.z); bp.w = fmaf(v, hi.y, bp.w);
    }

    // ---- stage 2: perspective combine + clamp ----
    const float u  = us[b];
    const float th = them[b];
    float4 a, c;
    a.x = clamp01(u * wp.x + th * bp.x);  c.x = clamp01(u * bp.x + th * wp.x);
    a.y = clamp01(u * wp.y + th * bp.y);  c.y = clamp01(u * bp.y + th * wp.y);
    a.z = clamp01(u * wp.z + th * bp.z);  c.z = clamp01(u * bp.z + th * wp.z);
    a.w = clamp01(u * wp.w + th * bp.w);  c.w = clamp01(u * bp.w + th * wp.w);
    reinterpret_cast<float4*>(s_a)[t] = a;
    reinterpret_cast<float4*>(s_b)[t] = c;
    __syncthreads();

    // ---- stage 3: pairwise products ----
    #pragma unroll
    for (int cix = t; cix < 512; cix += 256) {
        s_l0p[cix]       = s_a[cix] * s_a[cix + 512] * FSC;
        s_l0p[cix + 512] = s_b[cix] * s_b[cix + 512] * FSC;
    }
    __syncthreads();

    // ---- stage 4: L1 — 16 coalesced dots of 1024 (transposed W1t) ----
    const int bucket = lsi[b];
    const float4 x4 = reinterpret_cast<const float4*>(s_l0p)[t];
    const float4* w1t = reinterpret_cast<const float4*>(
        g_W1t + (size_t)bucket * 16 * L1DIM);

    #pragma unroll
    for (int j = 0; j < 16; j++) {
        const float4 w = w1t[j * (L1DIM / 4) + t];
        float v = x4.x * w.x + x4.y * w.y + x4.z * w.z + x4.w * w.w;
        #pragma unroll
        for (int o = 16; o > 0; o >>= 1)
            v += __shfl_xor_sync(0xffffffffu, v, o);
        if (lane == 0) s_part[j * 8 + warp] = v;
    }
    __syncthreads();

    if (t < 16) {
        float s = b1[bucket * 16 + t];
        #pragma unroll
        for (int w = 0; w < 8; w++) s += s_part[t * 8 + w];
        s_l1[t] = s;
    }
    __syncthreads();

    // ---- stage 5: L2 + L3 tail on warp 0 ----
    if (t < 32) {
        const float l1f = s_l1[15];          // pass-through term, NOT clipped
        float acc = b2[bucket * L3DIM + t];
        #pragma unroll
        for (int i = 0; i < L2DIM; i++) {
            const float x  = clamp01(s_l1[i]);
            const float wa = W2[(size_t)i * W2COLS + bucket * L3DIM + t];
            const float wb = W2[(size_t)(i + L2DIM) * W2COLS + bucket * L3DIM + t];
            acc = fmaf(x * x * FSC, wa, acc);
            acc = fmaf(x * FSC,     wb, acc);
        }
        const float l2x = clamp01(acc);
        float contrib = l2x * W3[t * NBUCK + bucket];
        #pragma unroll
        for (int o = 16; o > 0; o >>= 1)
            contrib += __shfl_xor_sync(0xffffffffu, contrib, o);
        if (t == 0) out[b] = contrib + b3[bucket] + l1f;
    }
}

extern "C" void kernel_launch(void* const* d_in, const int* in_sizes, int n_in,
                              void* d_out, int out_size) {
    const float* us   = (const float*)d_in[0];
    const float* them = (const float*)d_in[1];
    const int*   widx = (const int*)  d_in[2];
    const float* wval = (const float*)d_in[3];
    const int*   bidx = (const int*)  d_in[4];
    const float* bval = (const float*)d_in[5];
    const int*   lsi  = (const int*)  d_in[6];
    const float* W_ft = (const float*)d_in[7];
    const float* b_ft = (const float*)d_in[8];
    const float* W1   = (const float*)d_in[9];
    const float* b1   = (const float*)d_in[10];
    const float* W2   = (const float*)d_in[11];
    const float* b2   = (const float*)d_in[12];
    const float* W3   = (const float*)d_in[13];
    const float* b3   = (const float*)d_in[14];
    float* out = (float*)d_out;

    const int B = in_sizes[0];

    // prologues (stream-ordered before main kernel)
    convert_wft_kernel<<<2048, 256>>>(W_ft);
    transpose_w1_kernel<<<(NBUCK * 16 * L1DIM + 255) / 256, 256>>>(W1);

    nnue_fused_kernel<<<B, 256>>>(us, them, widx, wval, bidx, bval, lsi,
                                  b_ft, b1, W2, b2, W3, b3, out);
}

// round 7
// speedup vs baseline: 1.6306x; 1.1304x over previous
#include <cuda_runtime.h>
#include <cuda_fp16.h>

// NNUE forward, fused. v3:
//  - prologue A: W_ft fp32 -> fp16 scratch (halves gather traffic), __ldcs source reads
//  - prologue B: W1 transposed AND fp16: [bucket][j][e] (halves L1-layer traffic)
//  - main: one CTA per batch row, all intermediate state in regs/SMEM
//
// Inputs (metadata order):
//  0 us(B) 1 them(B) 2 white_indices(B*32 i32) 3 white_values(B*32)
//  4 black_indices 5 black_values 6 layer_stack_indices(B i32)
//  7 W_ft(22528*1024) 8 b_ft(1024) 9 W1(1024*144) 10 b1(144)
// 11 W2(30*288) 12 b2(288) 13 W3(32*9) 14 b3(9)

#define KIDX   32
#define L1DIM  1024
#define L2DIM  15
#define L3DIM  32
#define NBUCK  9
#define NF     22528
#define W1COLS (NBUCK * (L2DIM + 1))   // 144
#define W2COLS (NBUCK * L3DIM)         // 288
#define FSC    (127.0f / 128.0f)

struct __align__(8) Half4 { __half2 a, b; };

__device__ Half4 g_Wft16[(size_t)NF * L1DIM / 4];   // 46 MB fp16 copy of W_ft
__device__ Half4 g_W1t16[NBUCK * 16 * L1DIM / 4];   // 288 KB fp16 [bucket][j][e]

static __device__ __forceinline__ float clamp01(float x) {
    return fminf(fmaxf(x, 0.0f), 1.0f);
}

// ---------------- prologue A: fp32 -> fp16 convert (streaming reads) ----------------
__global__ __launch_bounds__(256)
void convert_wft_kernel(const float* __restrict__ W_ft) {
    const size_t n4 = (size_t)NF * L1DIM / 4;
    const float4* src = reinterpret_cast<const float4*>(W_ft);
    size_t i = (size_t)blockIdx.x * blockDim.x + threadIdx.x;
    const size_t stride = (size_t)gridDim.x * blockDim.x;
    for (; i < n4; i += stride) {
        float4 v = __ldcs(&src[i]);     // evict-first: don't displace g_Wft16 in L2
        Half4 h;
        h.a = __floats2half2_rn(v.x, v.y);
        h.b = __floats2half2_rn(v.z, v.w);
        g_Wft16[i] = h;
    }
}

// ---------------- prologue B: W1 transpose + fp16 ----------------
__global__ __launch_bounds__(256)
void transpose_w1_kernel(const float* __restrict__ W1) {
    const int n = NBUCK * 16 * L1DIM;
    int i = blockIdx.x * blockDim.x + threadIdx.x;
    if (i < n) {
        const int e   = i & (L1DIM - 1);
        const int j   = (i >> 10) & 15;
        const int bkt = i >> 14;
        reinterpret_cast<__half*>(g_W1t16)[i] =
            __float2half_rn(W1[(size_t)e * W1COLS + bkt * 16 + j]);
    }
}

// ---------------- main fused kernel ----------------
__global__ __launch_bounds__(256, 4)
void nnue_fused_kernel(
    const float* __restrict__ us,   const float* __restrict__ them,
    const int*   __restrict__ widx, const float* __restrict__ wval,
    const int*   __restrict__ bidx, const float* __restrict__ bval,
    const int*   __restrict__ lsi,
    const float* __restrict__ b_ft,
    const float* __restrict__ b1,
    const float* __restrict__ W2,   const float* __restrict__ b2,
    const float* __restrict__ W3,   const float* __restrict__ b3,
    float* __restrict__ out)
{
    const int b = blockIdx.x;
    const int t = threadIdx.x;          // 0..255, owns columns 4t..4t+3
    const int warp = t >> 5;
    const int lane = t & 31;

    __shared__ int   s_idx[2 * KIDX];
    __shared__ float s_val[2 * KIDX];
    __shared__ float s_a[L1DIM];        // l0 first half  (clamped)
    __shared__ float s_b[L1DIM];        // l0 second half (clamped)
    __shared__ float s_l0p[L1DIM];      // pairwise-product activation
    __shared__ float s_part[16 * 8];    // per-warp L1 partials
    __shared__ float s_l1[16];          // l1c bucket slice

    // ---- stage 0: indices/values into SMEM ----
    if (t < KIDX) {
        s_idx[t] = widx[b * KIDX + t];
        s_val[t] = wval[b * KIDX + t];
    } else if (t < 2 * KIDX) {
        s_idx[t] = bidx[b * KIDX + (t - KIDX)];
        s_val[t] = bval[b * KIDX + (t - KIDX)];
    }
    __syncthreads();

    // ---- stage 1: fp16 feature-transform gather/accumulate (fp32 math) ----
    const float4* bft4 = reinterpret_cast<const float4*>(b_ft);
    float4 wp = bft4[t];
    float4 bp = wp;

    #pragma unroll 8
    for (int k = 0; k < KIDX; k++) {
        const Half4* row = g_Wft16 + (size_t)s_idx[k] * (L1DIM / 4);
        const float  v = s_val[k];
        const Half4  r = row[t];
        const float2 lo = __half22float2(r.a);
        const float2 hi = __half22float2(r.b);
        wp.x = fmaf(v, lo.x, wp.x); wp.y = fmaf(v, lo.y, wp.y);
        wp.z = fmaf(v, hi.x, wp.z); wp.w = fmaf(v, hi.y, wp.w);
    }
    #pragma unroll 8
    for (int k = KIDX; k < 2 * KIDX; k++) {
        const Half4* row = g_Wft16 + (size_t)s_idx[k] * (L1DIM / 4);
        const float  v = s_val[k];
        const Half4  r = row[t];
        const float2 lo = __half22float2(r.a);
        const float2 hi = __half22float2(r.b);
        bp.x = fmaf(v, lo.x, bp.x); bp.y = fmaf(v, lo.y, bp.y);
        bp.z = fmaf(v, hi.x, bp.z); bp.w = fmaf(v, hi.y, bp.w);
    }

    // ---- stage 2: perspective combine + clamp ----
    const float u  = us[b];
    const float th = them[b];
    float4 a, c;
    a.x = clamp01(u * wp.x + th * bp.x);  c.x = clamp01(u * bp.x + th * wp.x);
    a.y = clamp01(u * wp.y + th * bp.y);  c.y = clamp01(u * bp.y + th * wp.y);
    a.z = clamp01(u * wp.z + th * bp.z);  c.z = clamp01(u * bp.z + th * wp.z);
    a.w = clamp01(u * wp.w + th * bp.w);  c.w = clamp01(u * bp.w + th * wp.w);
    reinterpret_cast<float4*>(s_a)[t] = a;
    reinterpret_cast<float4*>(s_b)[t] = c;
    __syncthreads();

    // ---- stage 3: pairwise products ----
    #pragma unroll
    for (int cix = t; cix < 512; cix += 256) {
        s_l0p[cix]       = s_a[cix] * s_a[cix + 512] * FSC;
        s_l0p[cix + 512] = s_b[cix] * s_b[cix + 512] * FSC;
    }
    __syncthreads();

    // ---- stage 4: L1 — 16 coalesced fp16 dots of 1024 ----
    const int bucket = lsi[b];
    const float4 x4 = reinterpret_cast<const float4*>(s_l0p)[t];
    const Half4* w1t = g_W1t16 + (size_t)bucket * 16 * (L1DIM / 4);

    #pragma unroll
    for (int j = 0; j < 16; j++) {
        const Half4 w = w1t[j * (L1DIM / 4) + t];
        const float2 lo = __half22float2(w.a);
        const float2 hi = __half22float2(w.b);
        float v = x4.x * lo.x + x4.y * lo.y + x4.z * hi.x + x4.w * hi.y;
        #pragma unroll
        for (int o = 16; o > 0; o >>= 1)
            v += __shfl_xor_sync(0xffffffffu, v, o);
        if (lane == 0) s_part[j * 8 + warp] = v;
    }
    __syncthreads();

    if (t < 16) {
        float s = b1[bucket * 16 + t];
        #pragma unroll
        for (int w = 0; w < 8; w++) s += s_part[t * 8 + w];
        s_l1[t] = s;
    }
    __syncthreads();

    // ---- stage 5: L2 + L3 tail on warp 0 ----
    if (t < 32) {
        const float l1f = s_l1[15];          // pass-through term, NOT clipped
        float acc = b2[bucket * L3DIM + t];
        #pragma unroll
        for (int i = 0; i < L2DIM; i++) {
            const float x  = clamp01(s_l1[i]);
            const float wa = W2[(size_t)i * W2COLS + bucket * L3DIM + t];
            const float wb = W2[(size_t)(i + L2DIM) * W2COLS + bucket * L3DIM + t];
            acc = fmaf(x * x * FSC, wa, acc);
            acc = fmaf(x * FSC,     wb, acc);
        }
        const float l2x = clamp01(acc);
        float contrib = l2x * W3[t * NBUCK + bucket];
        #pragma unroll
        for (int o = 16; o > 0; o >>= 1)
            contrib += __shfl_xor_sync(0xffffffffu, contrib, o);
        if (t == 0) out[b] = contrib + b3[bucket] + l1f;
    }
}

extern "C" void kernel_launch(void* const* d_in, const int* in_sizes, int n_in,
                              void* d_out, int out_size) {
    const float* us   = (const float*)d_in[0];
    const float* them = (const float*)d_in[1];
    const int*   widx = (const int*)  d_in[2];
    const float* wval = (const float*)d_in[3];
    const int*   bidx = (const int*)  d_in[4];
    const float* bval = (const float*)d_in[5];
    const int*   lsi  = (const int*)  d_in[6];
    const float* W_ft = (const float*)d_in[7];
    const float* b_ft = (const float*)d_in[8];
    const float* W1   = (const float*)d_in[9];
    const float* b1   = (const float*)d_in[10];
    const float* W2   = (const float*)d_in[11];
    const float* b2   = (const float*)d_in[12];
    const float* W3   = (const float*)d_in[13];
    const float* b3   = (const float*)d_in[14];
    float* out = (float*)d_out;

    const int B = in_sizes[0];

    // prologues (stream-ordered before main kernel)
    convert_wft_kernel<<<2048, 256>>>(W_ft);
    transpose_w1_kernel<<<(NBUCK * 16 * L1DIM + 255) / 256, 256>>>(W1);

    nnue_fused_kernel<<<B, 256>>>(us, them, widx, wval, bidx, bval, lsi,
                                  b_ft, b1, W2, b2, W3, b3, out);
}

// round 8
// speedup vs baseline: 1.7378x; 1.0658x over previous
#include <cuda_runtime.h>
#include <cuda_fp16.h>

// NNUE forward, fused. v4:
//  - single prologue kernel: W_ft fp32->fp16 (flat, 4-way ILP, streaming loads)
//    + W1 transpose-to-fp16 folded into trailing blocks
//  - main: one CTA per batch row (unchanged from v3 @ ~57us, near L2 ceiling)
//
// Inputs (metadata order):
//  0 us(B) 1 them(B) 2 white_indices(B*32 i32) 3 white_values(B*32)
//  4 black_indices 5 black_values 6 layer_stack_indices(B i32)
//  7 W_ft(22528*1024) 8 b_ft(1024) 9 W1(1024*144) 10 b1(144)
// 11 W2(30*288) 12 b2(288) 13 W3(32*9) 14 b3(9)

#define KIDX   32
#define L1DIM  1024
#define L2DIM  15
#define L3DIM  32
#define NBUCK  9
#define NF     22528
#define W1COLS (NBUCK * (L2DIM + 1))   // 144
#define W2COLS (NBUCK * L3DIM)         // 288
#define FSC    (127.0f / 128.0f)

#define N4      ((size_t)NF * L1DIM / 4)       // 5,767,168 Half4 elements
#define CHUNK   (N4 / 4)                        // 1,441,792
#define CONV_BLOCKS ((int)(CHUNK / 256))        // 5632
#define W1N     (NBUCK * 16 * L1DIM)            // 147,456
#define W1_BLOCKS ((W1N + 255) / 256)           // 576

struct __align__(8) Half4 { __half2 a, b; };

__device__ Half4 g_Wft16[N4];                   // 46 MB fp16 copy of W_ft
__device__ Half4 g_W1t16[W1N / 4];              // 288 KB fp16 [bucket][j][e]

static __device__ __forceinline__ float clamp01(float x) {
    return fminf(fmaxf(x, 0.0f), 1.0f);
}

static __device__ __forceinline__ Half4 cvt4(float4 v) {
    Half4 h;
    h.a = __floats2half2_rn(v.x, v.y);
    h.b = __floats2half2_rn(v.z, v.w);
    return h;
}

// ---------------- prologue: convert W_ft (blocks [0,CONV_BLOCKS)) ----------------
// ----------------         + transpose W1 (blocks [CONV_BLOCKS, +W1_BLOCKS)) ------
__global__ __launch_bounds__(256)
void prologue_kernel(const float* __restrict__ W_ft,
                     const float* __restrict__ W1) {
    if (blockIdx.x < CONV_BLOCKS) {
        const size_t g = (size_t)blockIdx.x * 256 + threadIdx.x;
        const float4* src = reinterpret_cast<const float4*>(W_ft);
        // 4 independent load->convert->store chains (MLP=4), warp-contiguous.
        const float4 v0 = __ldcs(&src[g]);
        const float4 v1 = __ldcs(&src[g + CHUNK]);
        const float4 v2 = __ldcs(&src[g + 2 * CHUNK]);
        const float4 v3 = __ldcs(&src[g + 3 * CHUNK]);
        g_Wft16[g]             = cvt4(v0);
        g_Wft16[g + CHUNK]     = cvt4(v1);
        g_Wft16[g + 2 * CHUNK] = cvt4(v2);
        g_Wft16[g + 3 * CHUNK] = cvt4(v3);
    } else {
        const int i = (blockIdx.x - CONV_BLOCKS) * 256 + threadIdx.x;
        if (i < W1N) {
            const int e   = i & (L1DIM - 1);
            const int j   = (i >> 10) & 15;
            const int bkt = i >> 14;
            reinterpret_cast<__half*>(g_W1t16)[i] =
                __float2half_rn(W1[(size_t)e * W1COLS + bkt * 16 + j]);
        }
    }
}

// ---------------- main fused kernel (unchanged from v3) ----------------
__global__ __launch_bounds__(256, 4)
void nnue_fused_kernel(
    const float* __restrict__ us,   const float* __restrict__ them,
    const int*   __restrict__ widx, const float* __restrict__ wval,
    const int*   __restrict__ bidx, const float* __restrict__ bval,
    const int*   __restrict__ lsi,
    const float* __restrict__ b_ft,
    const float* __restrict__ b1,
    const float* __restrict__ W2,   const float* __restrict__ b2,
    const float* __restrict__ W3,   const float* __restrict__ b3,
    float* __restrict__ out)
{
    const int b = blockIdx.x;
    const int t = threadIdx.x;          // 0..255, owns columns 4t..4t+3
    const int warp = t >> 5;
    const int lane = t & 31;

    __shared__ int   s_idx[2 * KIDX];
    __shared__ float s_val[2 * KIDX];
    __shared__ float s_a[L1DIM];        // l0 first half  (clamped)
    __shared__ float s_b[L1DIM];        // l0 second half (clamped)
    __shared__ float s_l0p[L1DIM];      // pairwise-product activation
    __shared__ float s_part[16 * 8];    // per-warp L1 partials
    __shared__ float s_l1[16];          // l1c bucket slice

    // ---- stage 0: indices/values into SMEM ----
    if (t < KIDX) {
        s_idx[t] = widx[b * KIDX + t];
        s_val[t] = wval[b * KIDX + t];
    } else if (t < 2 * KIDX) {
        s_idx[t] = bidx[b * KIDX + (t - KIDX)];
        s_val[t] = bval[b * KIDX + (t - KIDX)];
    }
    __syncthreads();

    // ---- stage 1: fp16 feature-transform gather/accumulate (fp32 math) ----
    const float4* bft4 = reinterpret_cast<const float4*>(b_ft);
    float4 wp = bft4[t];
    float4 bp = wp;

    #pragma unroll 8
    for (int k = 0; k < KIDX; k++) {
        const Half4* row = g_Wft16 + (size_t)s_idx[k] * (L1DIM / 4);
        const float  v = s_val[k];
        const Half4  r = row[t];
        const float2 lo = __half22float2(r.a);
        const float2 hi = __half22float2(r.b);
        wp.x = fmaf(v, lo.x, wp.x); wp.y = fmaf(v, lo.y, wp.y);
        wp.z = fmaf(v, hi.x, wp.z); wp.w = fmaf(v, hi.y, wp.w);
    }
    #pragma unroll 8
    for (int k = KIDX; k < 2 * KIDX; k++) {
        const Half4* row = g_Wft16 + (size_t)s_idx[k] * (L1DIM / 4);
        const float  v = s_val[k];
        const Half4  r = row[t];
        const float2 lo = __half22float2(r.a);
        const float2 hi = __half22float2(r.b);
        bp.x = fmaf(v, lo.x, bp.x); bp.y = fmaf(v, lo.y, bp.y);
        bp.z = fmaf(v, hi.x, bp.z); bp.w = fmaf(v, hi.y, bp.w);
    }

    // ---- stage 2: perspective combine + clamp ----
    const float u  = us[b];
    const float th = them[b];
    float4 a, c;
    a.x = clamp01(u * wp.x + th * bp.x);  c.x = clamp01(u * bp.x + th * wp.x);
    a.y = clamp01(u * wp.y + th * bp.y);  c.y = clamp01(u * bp.y + th * wp.y);
    a.z = clamp01(u * wp.z + th * bp.z);  c.z = clamp01(u * bp.z + th * wp.z);
    a.w = clamp01(u * wp.w + th * bp.w);  c.w = clamp01(u * bp.w + th * wp.w);
    reinterpret_cast<float4*>(s_a)[t] = a;
    reinterpret_cast<float4*>(s_b)[t] = c;
    __syncthreads();

    // ---- stage 3: pairwise products ----
    #pragma unroll
    for (int cix = t; cix < 512; cix += 256) {
        s_l0p[cix]       = s_a[cix] * s_a[cix + 512] * FSC;
        s_l0p[cix + 512] = s_b[cix] * s_b[cix + 512] * FSC;
    }
    __syncthreads();

    // ---- stage 4: L1 — 16 coalesced fp16 dots of 1024 ----
    const int bucket = lsi[b];
    const float4 x4 = reinterpret_cast<const float4*>(s_l0p)[t];
    const Half4* w1t = g_W1t16 + (size_t)bucket * 16 * (L1DIM / 4);

    #pragma unroll
    for (int j = 0; j < 16; j++) {
        const Half4 w = w1t[j * (L1DIM / 4) + t];
        const float2 lo = __half22float2(w.a);
        const float2 hi = __half22float2(w.b);
        float v = x4.x * lo.x + x4.y * lo.y + x4.z * hi.x + x4.w * hi.y;
        #pragma unroll
        for (int o = 16; o > 0; o >>= 1)
            v += __shfl_xor_sync(0xffffffffu, v, o);
        if (lane == 0) s_part[j * 8 + warp] = v;
    }
    __syncthreads();

    if (t < 16) {
        float s = b1[bucket * 16 + t];
        #pragma unroll
        for (int w = 0; w < 8; w++) s += s_part[t * 8 + w];
        s_l1[t] = s;
    }
    __syncthreads();

    // ---- stage 5: L2 + L3 tail on warp 0 ----
    if (t < 32) {
        const float l1f = s_l1[15];          // pass-through term, NOT clipped
        float acc = b2[bucket * L3DIM + t];
        #pragma unroll
        for (int i = 0; i < L2DIM; i++) {
            const float x  = clamp01(s_l1[i]);
            const float wa = W2[(size_t)i * W2COLS + bucket * L3DIM + t];
            const float wb = W2[(size_t)(i + L2DIM) * W2COLS + bucket * L3DIM + t];
            acc = fmaf(x * x * FSC, wa, acc);
            acc = fmaf(x * FSC,     wb, acc);
        }
        const float l2x = clamp01(acc);
        float contrib = l2x * W3[t * NBUCK + bucket];
        #pragma unroll
        for (int o = 16; o > 0; o >>= 1)
            contrib += __shfl_xor_sync(0xffffffffu, contrib, o);
        if (t == 0) out[b] = contrib + b3[bucket] + l1f;
    }
}

extern "C" void kernel_launch(void* const* d_in, const int* in_sizes, int n_in,
                              void* d_out, int out_size) {
    const float* us   = (const float*)d_in[0];
    const float* them = (const float*)d_in[1];
    const int*   widx = (const int*)  d_in[2];
    const float* wval = (const float*)d_in[3];
    const int*   bidx = (const int*)  d_in[4];
    const float* bval = (const float*)d_in[5];
    const int*   lsi  = (const int*)  d_in[6];
    const float* W_ft = (const float*)d_in[7];
    const float* b_ft = (const float*)d_in[8];
    const float* W1   = (const float*)d_in[9];
    const float* b1   = (const float*)d_in[10];
    const float* W2   = (const float*)d_in[11];
    const float* b2   = (const float*)d_in[12];
    const float* W3   = (const float*)d_in[13];
    const float* b3   = (const float*)d_in[14];
    float* out = (float*)d_out;

    const int B = in_sizes[0];

    prologue_kernel<<<CONV_BLOCKS + W1_BLOCKS, 256>>>(W_ft, W1);

    nnue_fused_kernel<<<B, 256>>>(us, them, widx, wval, bidx, bval, lsi,
                                  b_ft, b1, W2, b2, W3, b3, out);
}

// round 9
// speedup vs baseline: 1.9684x; 1.1327x over previous
#include <cuda_runtime.h>
#include <cuda_fp16.h>

// NNUE forward, fused. v5:
//  - prologue: W_ft fp32->fp16 (flat, 4-way ILP, streaming) + W1 transpose fp16
//  - main: one CTA per batch row; occupancy 6 CTAs/SM; stage-4 warp-per-2-outputs
//    mapping (10 SHFL/thread instead of 80)
//
// Inputs (metadata order):
//  0 us(B) 1 them(B) 2 white_indices(B*32 i32) 3 white_values(B*32)
//  4 black_indices 5 black_values 6 layer_stack_indices(B i32)
//  7 W_ft(22528*1024) 8 b_ft(1024) 9 W1(1024*144) 10 b1(144)
// 11 W2(30*288) 12 b2(288) 13 W3(32*9) 14 b3(9)

#define KIDX   32
#define L1DIM  1024
#define L2DIM  15
#define L3DIM  32
#define NBUCK  9
#define NF     22528
#define W1COLS (NBUCK * (L2DIM + 1))   // 144
#define W2COLS (NBUCK * L3DIM)         // 288
#define FSC    (127.0f / 128.0f)

#define N4      ((size_t)NF * L1DIM / 4)       // 5,767,168 Half4 elements
#define CHUNK   (N4 / 4)                        // 1,441,792
#define CONV_BLOCKS ((int)(CHUNK / 256))        // 5632
#define W1N     (NBUCK * 16 * L1DIM)            // 147,456
#define W1_BLOCKS ((W1N + 255) / 256)           // 576

struct __align__(8) Half4 { __half2 a, b; };

__device__ Half4 g_Wft16[N4];                   // 46 MB fp16 copy of W_ft
__device__ Half4 g_W1t16[W1N / 4];              // 288 KB fp16 [bucket][j][e]

static __device__ __forceinline__ float clamp01(float x) {
    return fminf(fmaxf(x, 0.0f), 1.0f);
}

static __device__ __forceinline__ Half4 cvt4(float4 v) {
    Half4 h;
    h.a = __floats2half2_rn(v.x, v.y);
    h.b = __floats2half2_rn(v.z, v.w);
    return h;
}

// ---------------- prologue: convert W_ft + transpose W1 ----------------
__global__ __launch_bounds__(256)
void prologue_kernel(const float* __restrict__ W_ft,
                     const float* __restrict__ W1) {
    if (blockIdx.x < CONV_BLOCKS) {
        const size_t g = (size_t)blockIdx.x * 256 + threadIdx.x;
        const float4* src = reinterpret_cast<const float4*>(W_ft);
        const float4 v0 = __ldcs(&src[g]);
        const float4 v1 = __ldcs(&src[g + CHUNK]);
        const float4 v2 = __ldcs(&src[g + 2 * CHUNK]);
        const float4 v3 = __ldcs(&src[g + 3 * CHUNK]);
        g_Wft16[g]             = cvt4(v0);
        g_Wft16[g + CHUNK]     = cvt4(v1);
        g_Wft16[g + 2 * CHUNK] = cvt4(v2);
        g_Wft16[g + 3 * CHUNK] = cvt4(v3);
    } else {
        const int i = (blockIdx.x - CONV_BLOCKS) * 256 + threadIdx.x;
        if (i < W1N) {
            const int e   = i & (L1DIM - 1);
            const int j   = (i >> 10) & 15;
            const int bkt = i >> 14;
            reinterpret_cast<__half*>(g_W1t16)[i] =
                __float2half_rn(W1[(size_t)e * W1COLS + bkt * 16 + j]);
        }
    }
}

// ---------------- main fused kernel ----------------
__global__ __launch_bounds__(256, 6)
void nnue_fused_kernel(
    const float* __restrict__ us,   const float* __restrict__ them,
    const int*   __restrict__ widx, const float* __restrict__ wval,
    const int*   __restrict__ bidx, const float* __restrict__ bval,
    const int*   __restrict__ lsi,
    const float* __restrict__ b_ft,
    const float* __restrict__ b1,
    const float* __restrict__ W2,   const float* __restrict__ b2,
    const float* __restrict__ W3,   const float* __restrict__ b3,
    float* __restrict__ out)
{
    const int b = blockIdx.x;
    const int t = threadIdx.x;          // 0..255, owns columns 4t..4t+3
    const int warp = t >> 5;
    const int lane = t & 31;

    __shared__ int   s_idx[2 * KIDX];
    __shared__ float s_val[2 * KIDX];
    __shared__ float s_a[L1DIM];        // l0 first half  (clamped)
    __shared__ float s_b[L1DIM];        // l0 second half (clamped)
    __shared__ float s_l0p[L1DIM];      // pairwise-product activation
    __shared__ float s_l1[16];          // l1c bucket slice

    // ---- stage 0: indices/values into SMEM ----
    if (t < KIDX) {
        s_idx[t] = widx[b * KIDX + t];
        s_val[t] = wval[b * KIDX + t];
    } else if (t < 2 * KIDX) {
        s_idx[t] = bidx[b * KIDX + (t - KIDX)];
        s_val[t] = bval[b * KIDX + (t - KIDX)];
    }
    __syncthreads();

    // ---- stage 1: fp16 feature-transform gather/accumulate (fp32 math) ----
    const float4* bft4 = reinterpret_cast<const float4*>(b_ft);
    float4 wp = bft4[t];
    float4 bp = wp;

    #pragma unroll 8
    for (int k = 0; k < KIDX; k++) {
        const Half4* row = g_Wft16 + (size_t)s_idx[k] * (L1DIM / 4);
        const float  v = s_val[k];
        const Half4  r = row[t];
        const float2 lo = __half22float2(r.a);
        const float2 hi = __half22float2(r.b);
        wp.x = fmaf(v, lo.x, wp.x); wp.y = fmaf(v, lo.y, wp.y);
        wp.z = fmaf(v, hi.x, wp.z); wp.w = fmaf(v, hi.y, wp.w);
    }
    #pragma unroll 8
    for (int k = KIDX; k < 2 * KIDX; k++) {
        const Half4* row = g_Wft16 + (size_t)s_idx[k] * (L1DIM / 4);
        const float  v = s_val[k];
        const Half4  r = row[t];
        const float2 lo = __half22float2(r.a);
        const float2 hi = __half22float2(r.b);
        bp.x = fmaf(v, lo.x, bp.x); bp.y = fmaf(v, lo.y, bp.y);
        bp.z = fmaf(v, hi.x, bp.z); bp.w = fmaf(v, hi.y, bp.w);
    }

    // ---- stage 2: perspective combine + clamp ----
    const float u  = us[b];
    const float th = them[b];
    float4 a, c;
    a.x = clamp01(u * wp.x + th * bp.x);  c.x = clamp01(u * bp.x + th * wp.x);
    a.y = clamp01(u * wp.y + th * bp.y);  c.y = clamp01(u * bp.y + th * wp.y);
    a.z = clamp01(u * wp.z + th * bp.z);  c.z = clamp01(u * bp.z + th * wp.z);
    a.w = clamp01(u * wp.w + th * bp.w);  c.w = clamp01(u * bp.w + th * wp.w);
    reinterpret_cast<float4*>(s_a)[t] = a;
    reinterpret_cast<float4*>(s_b)[t] = c;
    __syncthreads();

    // ---- stage 3: pairwise products ----
    #pragma unroll
    for (int cix = t; cix < 512; cix += 256) {
        s_l0p[cix]       = s_a[cix] * s_a[cix + 512] * FSC;
        s_l0p[cix + 512] = s_b[cix] * s_b[cix + 512] * FSC;
    }
    __syncthreads();

    // ---- stage 4: L1 — warp w computes outputs {2w, 2w+1} over 1024 elems ----
    const int bucket = lsi[b];
    {
        const Half4* wrow0 = g_W1t16
            + ((size_t)bucket * 16 + 2 * warp) * (L1DIM / 4);
        const Half4* wrow1 = wrow0 + (L1DIM / 4);
        const float4* x4 = reinterpret_cast<const float4*>(s_l0p);

        float v0 = 0.0f, v1 = 0.0f;
        #pragma unroll
        for (int i = 0; i < 8; i++) {
            const int e4 = i * 32 + lane;
            const float4 x  = x4[e4];
            const Half4  w0 = wrow0[e4];
            const Half4  w1 = wrow1[e4];
            const float2 l0 = __half22float2(w0.a);
            const float2 h0 = __half22float2(w0.b);
            const float2 l1 = __half22float2(w1.a);
            const float2 h1 = __half22float2(w1.b);
            v0 = fmaf(x.x, l0.x, v0); v0 = fmaf(x.y, l0.y, v0);
            v0 = fmaf(x.z, h0.x, v0); v0 = fmaf(x.w, h0.y, v0);
            v1 = fmaf(x.x, l1.x, v1); v1 = fmaf(x.y, l1.y, v1);
            v1 = fmaf(x.z, h1.x, v1); v1 = fmaf(x.w, h1.y, v1);
        }
        #pragma unroll
        for (int o = 16; o > 0; o >>= 1) {
            v0 += __shfl_xor_sync(0xffffffffu, v0, o);
            v1 += __shfl_xor_sync(0xffffffffu, v1, o);
        }
        if (lane == 0) {
            s_l1[2 * warp]     = v0 + b1[bucket * 16 + 2 * warp];
            s_l1[2 * warp + 1] = v1 + b1[bucket * 16 + 2 * warp + 1];
        }
    }
    __syncthreads();

    // ---- stage 5: L2 + L3 tail on warp 0 ----
    if (t < 32) {
        const float l1f = s_l1[15];          // pass-through term, NOT clipped
        float acc = b2[bucket * L3DIM + t];
        #pragma unroll
        for (int i = 0; i < L2DIM; i++) {
            const float x  = clamp01(s_l1[i]);
            const float wa = W2[(size_t)i * W2COLS + bucket * L3DIM + t];
            const float wb = W2[(size_t)(i + L2DIM) * W2COLS + bucket * L3DIM + t];
            acc = fmaf(x * x * FSC, wa, acc);
            acc = fmaf(x * FSC,     wb, acc);
        }
        const float l2x = clamp01(acc);
        float contrib = l2x * W3[t * NBUCK + bucket];
        #pragma unroll
        for (int o = 16; o > 0; o >>= 1)
            contrib += __shfl_xor_sync(0xffffffffu, contrib, o);
        if (t == 0) out[b] = contrib + b3[bucket] + l1f;
    }
}

extern "C" void kernel_launch(void* const* d_in, const int* in_sizes, int n_in,
                              void* d_out, int out_size) {
    const float* us   = (const float*)d_in[0];
    const float* them = (const float*)d_in[1];
    const int*   widx = (const int*)  d_in[2];
    const float* wval = (const float*)d_in[3];
    const int*   bidx = (const int*)  d_in[4];
    const float* bval = (const float*)d_in[5];
    const int*   lsi  = (const int*)  d_in[6];
    const float* W_ft = (const float*)d_in[7];
    const float* b_ft = (const float*)d_in[8];
    const float* W1   = (const float*)d_in[9];
    const float* b1   = (const float*)d_in[10];
    const float* W2   = (const float*)d_in[11];
    const float* b2   = (const float*)d_in[12];
    const float* W3   = (const float*)d_in[13];
    const float* b3   = (const float*)d_in[14];
    float* out = (float*)d_out;

    const int B = in_sizes[0];

    prologue_kernel<<<CONV_BLOCKS + W1_BLOCKS, 256>>>(W_ft, W1);

    nnue_fused_kernel<<<B, 256>>>(us, them, widx, wval, bidx, bval, lsi,
                                  b_ft, b1, W2, b2, W3, b3, out);
}

// round 10
// speedup vs baseline: 1.9743x; 1.0030x over previous
#include <cuda_runtime.h>
#include <cuda_fp16.h>

// NNUE forward, fused. v5:
//  - prologue: W_ft fp32->fp16 (flat, 4-way ILP, streaming) + W1 transpose fp16
//  - main: one CTA per batch row; occupancy 6 CTAs/SM; stage-4 warp-per-2-outputs
//    mapping (10 SHFL/thread instead of 80)
//
// Inputs (metadata order):
//  0 us(B) 1 them(B) 2 white_indices(B*32 i32) 3 white_values(B*32)
//  4 black_indices 5 black_values 6 layer_stack_indices(B i32)
//  7 W_ft(22528*1024) 8 b_ft(1024) 9 W1(1024*144) 10 b1(144)
// 11 W2(30*288) 12 b2(288) 13 W3(32*9) 14 b3(9)

#define KIDX   32
#define L1DIM  1024
#define L2DIM  15
#define L3DIM  32
#define NBUCK  9
#define NF     22528
#define W1COLS (NBUCK * (L2DIM + 1))   // 144
#define W2COLS (NBUCK * L3DIM)         // 288
#define FSC    (127.0f / 128.0f)

#define N4      ((size_t)NF * L1DIM / 4)       // 5,767,168 Half4 elements
#define CHUNK   (N4 / 4)                        // 1,441,792
#define CONV_BLOCKS ((int)(CHUNK / 256))        // 5632
#define W1N     (NBUCK * 16 * L1DIM)            // 147,456
#define W1_BLOCKS ((W1N + 255) / 256)           // 576

struct __align__(8) Half4 { __half2 a, b; };

__device__ Half4 g_Wft16[N4];                   // 46 MB fp16 copy of W_ft
__device__ Half4 g_W1t16[W1N / 4];              // 288 KB fp16 [bucket][j][e]

static __device__ __forceinline__ float clamp01(float x) {
    return fminf(fmaxf(x, 0.0f), 1.0f);
}

static __device__ __forceinline__ Half4 cvt4(float4 v) {
    Half4 h;
    h.a = __floats2half2_rn(v.x, v.y);
    h.b = __floats2half2_rn(v.z, v.w);
    return h;
}

// ---------------- prologue: convert W_ft + transpose W1 ----------------
__global__ __launch_bounds__(256)
void prologue_kernel(const float* __restrict__ W_ft,
                     const float* __restrict__ W1) {
    if (blockIdx.x < CONV_BLOCKS) {
        const size_t g = (size_t)blockIdx.x * 256 + threadIdx.x;
        const float4* src = reinterpret_cast<const float4*>(W_ft);
        const float4 v0 = __ldcs(&src[g]);
        const float4 v1 = __ldcs(&src[g + CHUNK]);
        const float4 v2 = __ldcs(&src[g + 2 * CHUNK]);
        const float4 v3 = __ldcs(&src[g + 3 * CHUNK]);
        g_Wft16[g]             = cvt4(v0);
        g_Wft16[g + CHUNK]     = cvt4(v1);
        g_Wft16[g + 2 * CHUNK] = cvt4(v2);
        g_Wft16[g + 3 * CHUNK] = cvt4(v3);
    } else {
        const int i = (blockIdx.x - CONV_BLOCKS) * 256 + threadIdx.x;
        if (i < W1N) {
            const int e   = i & (L1DIM - 1);
            const int j   = (i >> 10) & 15;
            const int bkt = i >> 14;
            reinterpret_cast<__half*>(g_W1t16)[i] =
                __float2half_rn(W1[(size_t)e * W1COLS + bkt * 16 + j]);
        }
    }
}

// ---------------- main fused kernel ----------------
__global__ __launch_bounds__(256, 6)
void nnue_fused_kernel(
    const float* __restrict__ us,   const float* __restrict__ them,
    const int*   __restrict__ widx, const float* __restrict__ wval,
    const int*   __restrict__ bidx, const float* __restrict__ bval,
    const int*   __restrict__ lsi,
    const float* __restrict__ b_ft,
    const float* __restrict__ b1,
    const float* __restrict__ W2,   const float* __restrict__ b2,
    const float* __restrict__ W3,   const float* __restrict__ b3,
    float* __restrict__ out)
{
    const int b = blockIdx.x;
    const int t = threadIdx.x;          // 0..255, owns columns 4t..4t+3
    const int warp = t >> 5;
    const int lane = t & 31;

    __shared__ int   s_idx[2 * KIDX];
    __shared__ float s_val[2 * KIDX];
    __shared__ float s_a[L1DIM];        // l0 first half  (clamped)
    __shared__ float s_b[L1DIM];        // l0 second half (clamped)
    __shared__ float s_l0p[L1DIM];      // pairwise-product activation
    __shared__ float s_l1[16];          // l1c bucket slice

    // ---- stage 0: indices/values into SMEM ----
    if (t < KIDX) {
        s_idx[t] = widx[b * KIDX + t];
        s_val[t] = wval[b * KIDX + t];
    } else if (t < 2 * KIDX) {
        s_idx[t] = bidx[b * KIDX + (t - KIDX)];
        s_val[t] = bval[b * KIDX + (t - KIDX)];
    }
    __syncthreads();

    // ---- stage 1: fp16 feature-transform gather/accumulate (fp32 math) ----
    const float4* bft4 = reinterpret_cast<const float4*>(b_ft);
    float4 wp = bft4[t];
    float4 bp = wp;

    #pragma unroll 8
    for (int k = 0; k < KIDX; k++) {
        const Half4* row = g_Wft16 + (size_t)s_idx[k] * (L1DIM / 4);
        const float  v = s_val[k];
        const Half4  r = row[t];
        const float2 lo = __half22float2(r.a);
        const float2 hi = __half22float2(r.b);
        wp.x = fmaf(v, lo.x, wp.x); wp.y = fmaf(v, lo.y, wp.y);
        wp.z = fmaf(v, hi.x, wp.z); wp.w = fmaf(v, hi.y, wp.w);
    }
    #pragma unroll 8
    for (int k = KIDX; k < 2 * KIDX; k++) {
        const Half4* row = g_Wft16 + (size_t)s_idx[k] * (L1DIM / 4);
        const float  v = s_val[k];
        const Half4  r = row[t];
        const float2 lo = __half22float2(r.a);
        const float2 hi = __half22float2(r.b);
        bp.x = fmaf(v, lo.x, bp.x); bp.y = fmaf(v, lo.y, bp.y);
        bp.z = fmaf(v, hi.x, bp.z); bp.w = fmaf(v, hi.y, bp.w);
    }

    // ---- stage 2: perspective combine + clamp ----
    const float u  = us[b];
    const float th = them[b];
    float4 a, c;
    a.x = clamp01(u * wp.x + th * bp.x);  c.x = clamp01(u * bp.x + th * wp.x);
    a.y = clamp01(u * wp.y + th * bp.y);  c.y = clamp01(u * bp.y + th * wp.y);
    a.z = clamp01(u * wp.z + th * bp.z);  c.z = clamp01(u * bp.z + th * wp.z);
    a.w = clamp01(u * wp.w + th * bp.w);  c.w = clamp01(u * bp.w + th * wp.w);
    reinterpret_cast<float4*>(s_a)[t] = a;
    reinterpret_cast<float4*>(s_b)[t] = c;
    __syncthreads();

    // ---- stage 3: pairwise products ----
    #pragma unroll
    for (int cix = t; cix < 512; cix += 256) {
        s_l0p[cix]       = s_a[cix] * s_a[cix + 512] * FSC;
        s_l0p[cix + 512] = s_b[cix] * s_b[cix + 512] * FSC;
    }
    __syncthreads();

    // ---- stage 4: L1 — warp w computes outputs {2w, 2w+1} over 1024 elems ----
    const int bucket = lsi[b];
    {
        const Half4* wrow0 = g_W1t16
            + ((size_t)bucket * 16 + 2 * warp) * (L1DIM / 4);
        const Half4* wrow1 = wrow0 + (L1DIM / 4);
        const float4* x4 = reinterpret_cast<const float4*>(s_l0p);

        float v0 = 0.0f, v1 = 0.0f;
        #pragma unroll
        for (int i = 0; i < 8; i++) {
            const int e4 = i * 32 + lane;
            const float4 x  = x4[e4];
            const Half4  w0 = wrow0[e4];
            const Half4  w1 = wrow1[e4];
            const float2 l0 = __half22float2(w0.a);
            const float2 h0 = __half22float2(w0.b);
            const float2 l1 = __half22float2(w1.a);
            const float2 h1 = __half22float2(w1.b);
            v0 = fmaf(x.x, l0.x, v0); v0 = fmaf(x.y, l0.y, v0);
            v0 = fmaf(x.z, h0.x, v0); v0 = fmaf(x.w, h0.y, v0);
            v1 = fmaf(x.x, l1.x, v1); v1 = fmaf(x.y, l1.y, v1);
            v1 = fmaf(x.z, h1.x, v1); v1 = fmaf(x.w, h1.y, v1);
        }
        #pragma unroll
        for (int o = 16; o > 0; o >>= 1) {
            v0 += __shfl_xor_sync(0xffffffffu, v0, o);
            v1 += __shfl_xor_sync(0xffffffffu, v1, o);
        }
        if (lane == 0) {
            s_l1[2 * warp]     = v0 + b1[bucket * 16 + 2 * warp];
            s_l1[2 * warp + 1] = v1 + b1[bucket * 16 + 2 * warp + 1];
        }
    }
    __syncthreads();

    // ---- stage 5: L2 + L3 tail on warp 0 ----
    if (t < 32) {
        const float l1f = s_l1[15];          // pass-through term, NOT clipped
        float acc = b2[bucket * L3DIM + t];
        #pragma unroll
        for (int i = 0; i < L2DIM; i++) {
            const float x  = clamp01(s_l1[i]);
            const float wa = W2[(size_t)i * W2COLS + bucket * L3DIM + t];
            const float wb = W2[(size_t)(i + L2DIM) * W2COLS + bucket * L3DIM + t];
            acc = fmaf(x * x * FSC, wa, acc);
            acc = fmaf(x * FSC,     wb, acc);
        }
        const float l2x = clamp01(acc);
        float contrib = l2x * W3[t * NBUCK + bucket];
        #pragma unroll
        for (int o = 16; o > 0; o >>= 1)
            contrib += __shfl_xor_sync(0xffffffffu, contrib, o);
        if (t == 0) out[b] = contrib + b3[bucket] + l1f;
    }
}

extern "C" void kernel_launch(void* const* d_in, const int* in_sizes, int n_in,
                              void* d_out, int out_size) {
    const float* us   = (const float*)d_in[0];
    const float* them = (const float*)d_in[1];
    const int*   widx = (const int*)  d_in[2];
    const float* wval = (const float*)d_in[3];
    const int*   bidx = (const int*)  d_in[4];
    const float* bval = (const float*)d_in[5];
    const int*   lsi  = (const int*)  d_in[6];
    const float* W_ft = (const float*)d_in[7];
    const float* b_ft = (const float*)d_in[8];
    const float* W1   = (const float*)d_in[9];
    const float* b1   = (const float*)d_in[10];
    const float* W2   = (const float*)d_in[11];
    const float* b2   = (const float*)d_in[12];
    const float* W3   = (const float*)d_in[13];
    const float* b3   = (const float*)d_in[14];
    float* out = (float*)d_out;

    const int B = in_sizes[0];

    prologue_kernel<<<CONV_BLOCKS + W1_BLOCKS, 256>>>(W_ft, W1);

    nnue_fused_kernel<<<B, 256>>>(us, them, widx, wval, bidx, bval, lsi,
                                  b_ft, b1, W2, b2, W3, b3, out);
}

// round 11
// speedup vs baseline: 1.9950x; 1.0105x over previous
#include <cuda_runtime.h>
#include <cuda_fp16.h>

// NNUE forward, fused. v5:
//  - prologue: W_ft fp32->fp16 (flat, 4-way ILP, streaming) + W1 transpose fp16
//  - main: one CTA per batch row; occupancy 6 CTAs/SM; stage-4 warp-per-2-outputs
//    mapping (10 SHFL/thread instead of 80)
//
// Inputs (metadata order):
//  0 us(B) 1 them(B) 2 white_indices(B*32 i32) 3 white_values(B*32)
//  4 black_indices 5 black_values 6 layer_stack_indices(B i32)
//  7 W_ft(22528*1024) 8 b_ft(1024) 9 W1(1024*144) 10 b1(144)
// 11 W2(30*288) 12 b2(288) 13 W3(32*9) 14 b3(9)

#define KIDX   32
#define L1DIM  1024
#define L2DIM  15
#define L3DIM  32
#define NBUCK  9
#define NF     22528
#define W1COLS (NBUCK * (L2DIM + 1))   // 144
#define W2COLS (NBUCK * L3DIM)         // 288
#define FSC    (127.0f / 128.0f)

#define N4      ((size_t)NF * L1DIM / 4)       // 5,767,168 Half4 elements
#define CHUNK   (N4 / 4)                        // 1,441,792
#define CONV_BLOCKS ((int)(CHUNK / 256))        // 5632
#define W1N     (NBUCK * 16 * L1DIM)            // 147,456
#define W1_BLOCKS ((W1N + 255) / 256)           // 576

struct __align__(8) Half4 { __half2 a, b; };

__device__ Half4 g_Wft16[N4];                   // 46 MB fp16 copy of W_ft
__device__ Half4 g_W1t16[W1N / 4];              // 288 KB fp16 [bucket][j][e]

static __device__ __forceinline__ float clamp01(float x) {
    return fminf(fmaxf(x, 0.0f), 1.0f);
}

static __device__ __forceinline__ Half4 cvt4(float4 v) {
    Half4 h;
    h.a = __floats2half2_rn(v.x, v.y);
    h.b = __floats2half2_rn(v.z, v.w);
    return h;
}

// ---------------- prologue: convert W_ft + transpose W1 ----------------
__global__ __launch_bounds__(256)
void prologue_kernel(const float* __restrict__ W_ft,
                     const float* __restrict__ W1) {
    if (blockIdx.x < CONV_BLOCKS) {
        const size_t g = (size_t)blockIdx.x * 256 + threadIdx.x;
        const float4* src = reinterpret_cast<const float4*>(W_ft);
        const float4 v0 = __ldcs(&src[g]);
        const float4 v1 = __ldcs(&src[g + CHUNK]);
        const float4 v2 = __ldcs(&src[g + 2 * CHUNK]);
        const float4 v3 = __ldcs(&src[g + 3 * CHUNK]);
        g_Wft16[g]             = cvt4(v0);
        g_Wft16[g + CHUNK]     = cvt4(v1);
        g_Wft16[g + 2 * CHUNK] = cvt4(v2);
        g_Wft16[g + 3 * CHUNK] = cvt4(v3);
    } else {
        const int i = (blockIdx.x - CONV_BLOCKS) * 256 + threadIdx.x;
        if (i < W1N) {
            const int e   = i & (L1DIM - 1);
            const int j   = (i >> 10) & 15;
            const int bkt = i >> 14;
            reinterpret_cast<__half*>(g_W1t16)[i] =
                __float2half_rn(W1[(size_t)e * W1COLS + bkt * 16 + j]);
        }
    }
}

// ---------------- main fused kernel ----------------
__global__ __launch_bounds__(256, 6)
void nnue_fused_kernel(
    const float* __restrict__ us,   const float* __restrict__ them,
    const int*   __restrict__ widx, const float* __restrict__ wval,
    const int*   __restrict__ bidx, const float* __restrict__ bval,
    const int*   __restrict__ lsi,
    const float* __restrict__ b_ft,
    const float* __restrict__ b1,
    const float* __restrict__ W2,   const float* __restrict__ b2,
    const float* __restrict__ W3,   const float* __restrict__ b3,
    float* __restrict__ out)
{
    const int b = blockIdx.x;
    const int t = threadIdx.x;          // 0..255, owns columns 4t..4t+3
    const int warp = t >> 5;
    const int lane = t & 31;

    __shared__ int   s_idx[2 * KIDX];
    __shared__ float s_val[2 * KIDX];
    __shared__ float s_a[L1DIM];        // l0 first half  (clamped)
    __shared__ float s_b[L1DIM];        // l0 second half (clamped)
    __shared__ float s_l0p[L1DIM];      // pairwise-product activation
    __shared__ float s_l1[16];          // l1c bucket slice

    // ---- stage 0: indices/values into SMEM ----
    if (t < KIDX) {
        s_idx[t] = widx[b * KIDX + t];
        s_val[t] = wval[b * KIDX + t];
    } else if (t < 2 * KIDX) {
        s_idx[t] = bidx[b * KIDX + (t - KIDX)];
        s_val[t] = bval[b * KIDX + (t - KIDX)];
    }
    __syncthreads();

    // ---- stage 1: fp16 feature-transform gather/accumulate (fp32 math) ----
    const float4* bft4 = reinterpret_cast<const float4*>(b_ft);
    float4 wp = bft4[t];
    float4 bp = wp;

    #pragma unroll 8
    for (int k = 0; k < KIDX; k++) {
        const Half4* row = g_Wft16 + (size_t)s_idx[k] * (L1DIM / 4);
        const float  v = s_val[k];
        const Half4  r = row[t];
        const float2 lo = __half22float2(r.a);
        const float2 hi = __half22float2(r.b);
        wp.x = fmaf(v, lo.x, wp.x); wp.y = fmaf(v, lo.y, wp.y);
        wp.z = fmaf(v, hi.x, wp.z); wp.w = fmaf(v, hi.y, wp.w);
    }
    #pragma unroll 8
    for (int k = KIDX; k < 2 * KIDX; k++) {
        const Half4* row = g_Wft16 + (size_t)s_idx[k] * (L1DIM / 4);
        const float  v = s_val[k];
        const Half4  r = row[t];
        const float2 lo = __half22float2(r.a);
        const float2 hi = __half22float2(r.b);
        bp.x = fmaf(v, lo.x, bp.x); bp.y = fmaf(v, lo.y, bp.y);
        bp.z = fmaf(v, hi.x, bp.z); bp.w = fmaf(v, hi.y, bp.w);
    }

    // ---- stage 2: perspective combine + clamp ----
    const float u  = us[b];
    const float th = them[b];
    float4 a, c;
    a.x = clamp01(u * wp.x + th * bp.x);  c.x = clamp01(u * bp.x + th * wp.x);
    a.y = clamp01(u * wp.y + th * bp.y);  c.y = clamp01(u * bp.y + th * wp.y);
    a.z = clamp01(u * wp.z + th * bp.z);  c.z = clamp01(u * bp.z + th * wp.z);
    a.w = clamp01(u * wp.w + th * bp.w);  c.w = clamp01(u * bp.w + th * wp.w);
    reinterpret_cast<float4*>(s_a)[t] = a;
    reinterpret_cast<float4*>(s_b)[t] = c;
    __syncthreads();

    // ---- stage 3: pairwise products ----
    #pragma unroll
    for (int cix = t; cix < 512; cix += 256) {
        s_l0p[cix]       = s_a[cix] * s_a[cix + 512] * FSC;
        s_l0p[cix + 512] = s_b[cix] * s_b[cix + 512] * FSC;
    }
    __syncthreads();

    // ---- stage 4: L1 — warp w computes outputs {2w, 2w+1} over 1024 elems ----
    const int bucket = lsi[b];
    {
        const Half4* wrow0 = g_W1t16
            + ((size_t)bucket * 16 + 2 * warp) * (L1DIM / 4);
        const Half4* wrow1 = wrow0 + (L1DIM / 4);
        const float4* x4 = reinterpret_cast<const float4*>(s_l0p);

        float v0 = 0.0f, v1 = 0.0f;
        #pragma unroll
        for (int i = 0; i < 8; i++) {
            const int e4 = i * 32 + lane;
            const float4 x  = x4[e4];
            const Half4  w0 = wrow0[e4];
            const Half4  w1 = wrow1[e4];
            const float2 l0 = __half22float2(w0.a);
            const float2 h0 = __half22float2(w0.b);
            const float2 l1 = __half22float2(w1.a);
            const float2 h1 = __half22float2(w1.b);
            v0 = fmaf(x.x, l0.x, v0); v0 = fmaf(x.y, l0.y, v0);
            v0 = fmaf(x.z, h0.x, v0); v0 = fmaf(x.w, h0.y, v0);
            v1 = fmaf(x.x, l1.x, v1); v1 = fmaf(x.y, l1.y, v1);
            v1 = fmaf(x.z, h1.x, v1); v1 = fmaf(x.w, h1.y, v1);
        }
        #pragma unroll
        for (int o = 16; o > 0; o >>= 1) {
            v0 += __shfl_xor_sync(0xffffffffu, v0, o);
            v1 += __shfl_xor_sync(0xffffffffu, v1, o);
        }
        if (lane == 0) {
            s_l1[2 * warp]     = v0 + b1[bucket * 16 + 2 * warp];
            s_l1[2 * warp + 1] = v1 + b1[bucket * 16 + 2 * warp + 1];
        }
    }
    __syncthreads();

    // ---- stage 5: L2 + L3 tail on warp 0 ----
    if (t < 32) {
        const float l1f = s_l1[15];          // pass-through term, NOT clipped
        float acc = b2[bucket * L3DIM + t];
        #pragma unroll
        for (int i = 0; i < L2DIM; i++) {
            const float x  = clamp01(s_l1[i]);
            const float wa = W2[(size_t)i * W2COLS + bucket * L3DIM + t];
            const float wb = W2[(size_t)(i + L2DIM) * W2COLS + bucket * L3DIM + t];
            acc = fmaf(x * x * FSC, wa, acc);
            acc = fmaf(x * FSC,     wb, acc);
        }
        const float l2x = clamp01(acc);
        float contrib = l2x * W3[t * NBUCK + bucket];
        #pragma unroll
        for (int o = 16; o > 0; o >>= 1)
            contrib += __shfl_xor_sync(0xffffffffu, contrib, o);
        if (t == 0) out[b] = contrib + b3[bucket] + l1f;
    }
}

extern "C" void kernel_launch(void* const* d_in, const int* in_sizes, int n_in,
                              void* d_out, int out_size) {
    const float* us   = (const float*)d_in[0];
    const float* them = (const float*)d_in[1];
    const int*   widx = (const int*)  d_in[2];
    const float* wval = (const float*)d_in[3];
    const int*   bidx = (const int*)  d_in[4];
    const float* bval = (const float*)d_in[5];
    const int*   lsi  = (const int*)  d_in[6];
    const float* W_ft = (const float*)d_in[7];
    const float* b_ft = (const float*)d_in[8];
    const float* W1   = (const float*)d_in[9];
    const float* b1   = (const float*)d_in[10];
    const float* W2   = (const float*)d_in[11];
    const float* b2   = (const float*)d_in[12];
    const float* W3   = (const float*)d_in[13];
    const float* b3   = (const float*)d_in[14];
    float* out = (float*)d_out;

    const int B = in_sizes[0];

    prologue_kernel<<<CONV_BLOCKS + W1_BLOCKS, 256>>>(W_ft, W1);

    nnue_fused_kernel<<<B, 256>>>(us, them, widx, wval, bidx, bval, lsi,
                                  b_ft, b1, W2, b2, W3, b3, out);
}

// round 12
// speedup vs baseline: 2.0525x; 1.0288x over previous
#include <cuda_runtime.h>
#include <cuda_fp16.h>

// NNUE forward, fused. v6:
//  - prologue: W_ft fp32->fp16 (flat, 4-way ILP, streaming) + W1 transpose fp16
//  - main: one CTA per batch row; gather restructured to LDG.128 with a
//    wp/bp thread split (threads 0-127 white, 128-255 black; 8 cols/thread)
//    -> 32 iterations instead of 64, precomputed byte offsets.
//
// Inputs (metadata order):
//  0 us(B) 1 them(B) 2 white_indices(B*32 i32) 3 white_values(B*32)
//  4 black_indices 5 black_values 6 layer_stack_indices(B i32)
//  7 W_ft(22528*1024) 8 b_ft(1024) 9 W1(1024*144) 10 b1(144)
// 11 W2(30*288) 12 b2(288) 13 W3(32*9) 14 b3(9)

#define KIDX   32
#define L1DIM  1024
#define L2DIM  15
#define L3DIM  32
#define NBUCK  9
#define NF     22528
#define W1COLS (NBUCK * (L2DIM + 1))   // 144
#define W2COLS (NBUCK * L3DIM)         // 288
#define FSC    (127.0f / 128.0f)

#define N4      ((size_t)NF * L1DIM / 4)       // 5,767,168 Half4 elements
#define CHUNK   (N4 / 4)                        // 1,441,792
#define CONV_BLOCKS ((int)(CHUNK / 256))        // 5632
#define W1N     (NBUCK * 16 * L1DIM)            // 147,456
#define W1_BLOCKS ((W1N + 255) / 256)           // 576

struct __align__(8) Half4 { __half2 a, b; };

__device__ Half4 g_Wft16[N4];                   // 46 MB fp16 copy of W_ft
__device__ Half4 g_W1t16[W1N / 4];              // 288 KB fp16 [bucket][j][e]

static __device__ __forceinline__ float clamp01(float x) {
    return fminf(fmaxf(x, 0.0f), 1.0f);
}

static __device__ __forceinline__ Half4 cvt4(float4 v) {
    Half4 h;
    h.a = __floats2half2_rn(v.x, v.y);
    h.b = __floats2half2_rn(v.z, v.w);
    return h;
}

// ---------------- prologue: convert W_ft + transpose W1 ----------------
__global__ __launch_bounds__(256)
void prologue_kernel(const float* __restrict__ W_ft,
                     const float* __restrict__ W1) {
    if (blockIdx.x < CONV_BLOCKS) {
        const size_t g = (size_t)blockIdx.x * 256 + threadIdx.x;
        const float4* src = reinterpret_cast<const float4*>(W_ft);
        const float4 v0 = __ldcs(&src[g]);
        const float4 v1 = __ldcs(&src[g + CHUNK]);
        const float4 v2 = __ldcs(&src[g + 2 * CHUNK]);
        const float4 v3 = __ldcs(&src[g + 3 * CHUNK]);
        g_Wft16[g]             = cvt4(v0);
        g_Wft16[g + CHUNK]     = cvt4(v1);
        g_Wft16[g + 2 * CHUNK] = cvt4(v2);
        g_Wft16[g + 3 * CHUNK] = cvt4(v3);
    } else {
        const int i = (blockIdx.x - CONV_BLOCKS) * 256 + threadIdx.x;
        if (i < W1N) {
            const int e   = i & (L1DIM - 1);
            const int j   = (i >> 10) & 15;
            const int bkt = i >> 14;
            reinterpret_cast<__half*>(g_W1t16)[i] =
                __float2half_rn(W1[(size_t)e * W1COLS + bkt * 16 + j]);
        }
    }
}

// ---------------- main fused kernel ----------------
__global__ __launch_bounds__(256, 6)
void nnue_fused_kernel(
    const float* __restrict__ us,   const float* __restrict__ them,
    const int*   __restrict__ widx, const float* __restrict__ wval,
    const int*   __restrict__ bidx, const float* __restrict__ bval,
    const int*   __restrict__ lsi,
    const float* __restrict__ b_ft,
    const float* __restrict__ b1,
    const float* __restrict__ W2,   const float* __restrict__ b2,
    const float* __restrict__ W3,   const float* __restrict__ b3,
    float* __restrict__ out)
{
    const int b = blockIdx.x;
    const int t = threadIdx.x;
    const int warp = t >> 5;
    const int lane = t & 31;

    __shared__ unsigned s_off[2 * KIDX];   // byte offsets into g_Wft16
    __shared__ float    s_val[2 * KIDX];
    __shared__ float    s_a[L1DIM];        // wp -> A (in-place)
    __shared__ float    s_b[L1DIM];        // bp -> B (in-place)
    __shared__ float    s_l0p[L1DIM];      // pairwise-product activation
    __shared__ float    s_l1[16];          // l1c bucket slice

    // ---- stage 0: indices (as byte offsets) / values into SMEM ----
    if (t < KIDX) {
        s_off[t] = (unsigned)widx[b * KIDX + t] * (L1DIM * 2u);
        s_val[t] = wval[b * KIDX + t];
    } else if (t < 2 * KIDX) {
        s_off[t] = (unsigned)bidx[b * KIDX + (t - KIDX)] * (L1DIM * 2u);
        s_val[t] = bval[b * KIDX + (t - KIDX)];
    }
    __syncthreads();

    // ---- stage 1: gather/accumulate; threads 0-127: wp, 128-255: bp ----
    // each thread owns 8 columns: 8*tl .. 8*tl+7  (tl = t & 127)
    const int tl    = t & 127;
    const int kbase = (t < 128) ? 0 : KIDX;

    const float4* bft4 = reinterpret_cast<const float4*>(b_ft);
    float4 acc0 = bft4[2 * tl];
    float4 acc1 = bft4[2 * tl + 1];

    const char* wbase = reinterpret_cast<const char*>(g_Wft16);
    const unsigned lanebyte = (unsigned)tl * 16u;

    #pragma unroll 8
    for (int k = 0; k < KIDX; k++) {
        const unsigned off = s_off[kbase + k];
        const float    v   = s_val[kbase + k];
        const uint4 r = *reinterpret_cast<const uint4*>(wbase + off + lanebyte);
        const float2 p0 = __half22float2(*reinterpret_cast<const __half2*>(&r.x));
        const float2 p1 = __half22float2(*reinterpret_cast<const __half2*>(&r.y));
        const float2 p2 = __half22float2(*reinterpret_cast<const __half2*>(&r.z));
        const float2 p3 = __half22float2(*reinterpret_cast<const __half2*>(&r.w));
        acc0.x = fmaf(v, p0.x, acc0.x); acc0.y = fmaf(v, p0.y, acc0.y);
        acc0.z = fmaf(v, p1.x, acc0.z); acc0.w = fmaf(v, p1.y, acc0.w);
        acc1.x = fmaf(v, p2.x, acc1.x); acc1.y = fmaf(v, p2.y, acc1.y);
        acc1.z = fmaf(v, p3.x, acc1.z); acc1.w = fmaf(v, p3.y, acc1.w);
    }

    // stage raw wp into s_a (white threads), bp into s_b (black threads)
    {
        float4* dst = (t < 128) ? reinterpret_cast<float4*>(s_a)
                                : reinterpret_cast<float4*>(s_b);
        dst[2 * tl]     = acc0;
        dst[2 * tl + 1] = acc1;
    }
    __syncthreads();

    // ---- stage 2: perspective combine + clamp (in place, 4 cols/thread) ----
    const float u  = us[b];
    const float th = them[b];
    {
        float4* a4 = reinterpret_cast<float4*>(s_a);
        float4* b4 = reinterpret_cast<float4*>(s_b);
        const float4 wp = a4[t];
        const float4 bp = b4[t];
        float4 A, Bv;
        A.x  = clamp01(u * wp.x + th * bp.x);  Bv.x = clamp01(u * bp.x + th * wp.x);
        A.y  = clamp01(u * wp.y + th * bp.y);  Bv.y = clamp01(u * bp.y + th * wp.y);
        A.z  = clamp01(u * wp.z + th * bp.z);  Bv.z = clamp01(u * bp.z + th * wp.z);
        A.w  = clamp01(u * wp.w + th * bp.w);  Bv.w = clamp01(u * bp.w + th * wp.w);
        a4[t] = A;
        b4[t] = Bv;
    }
    __syncthreads();

    // ---- stage 3: pairwise products ----
    #pragma unroll
    for (int cix = t; cix < 512; cix += 256) {
        s_l0p[cix]       = s_a[cix] * s_a[cix + 512] * FSC;
        s_l0p[cix + 512] = s_b[cix] * s_b[cix + 512] * FSC;
    }
    __syncthreads();

    // ---- stage 4: L1 — warp w computes outputs {2w, 2w+1} over 1024 elems ----
    const int bucket = lsi[b];
    {
        const Half4* wrow0 = g_W1t16
            + ((size_t)bucket * 16 + 2 * warp) * (L1DIM / 4);
        const Half4* wrow1 = wrow0 + (L1DIM / 4);
        const float4* x4 = reinterpret_cast<const float4*>(s_l0p);

        float v0 = 0.0f, v1 = 0.0f;
        #pragma unroll
        for (int i = 0; i < 8; i++) {
            const int e4 = i * 32 + lane;
            const float4 x  = x4[e4];
            const Half4  w0 = wrow0[e4];
            const Half4  w1 = wrow1[e4];
            const float2 l0 = __half22float2(w0.a);
            const float2 h0 = __half22float2(w0.b);
            const float2 l1 = __half22float2(w1.a);
            const float2 h1 = __half22float2(w1.b);
            v0 = fmaf(x.x, l0.x, v0); v0 = fmaf(x.y, l0.y, v0);
            v0 = fmaf(x.z, h0.x, v0); v0 = fmaf(x.w, h0.y, v0);
            v1 = fmaf(x.x, l1.x, v1); v1 = fmaf(x.y, l1.y, v1);
            v1 = fmaf(x.z, h1.x, v1); v1 = fmaf(x.w, h1.y, v1);
        }
        #pragma unroll
        for (int o = 16; o > 0; o >>= 1) {
            v0 += __shfl_xor_sync(0xffffffffu, v0, o);
            v1 += __shfl_xor_sync(0xffffffffu, v1, o);
        }
        if (lane == 0) {
            s_l1[2 * warp]     = v0 + b1[bucket * 16 + 2 * warp];
            s_l1[2 * warp + 1] = v1 + b1[bucket * 16 + 2 * warp + 1];
        }
    }
    __syncthreads();

    // ---- stage 5: L2 + L3 tail on warp 0 ----
    if (t < 32) {
        const float l1f = s_l1[15];          // pass-through term, NOT clipped
        float acc = b2[bucket * L3DIM + t];
        #pragma unroll
        for (int i = 0; i < L2DIM; i++) {
            const float x  = clamp01(s_l1[i]);
            const float wa = W2[(size_t)i * W2COLS + bucket * L3DIM + t];
            const float wb = W2[(size_t)(i + L2DIM) * W2COLS + bucket * L3DIM + t];
            acc = fmaf(x * x * FSC, wa, acc);
            acc = fmaf(x * FSC,     wb, acc);
        }
        const float l2x = clamp01(acc);
        float contrib = l2x * W3[t * NBUCK + bucket];
        #pragma unroll
        for (int o = 16; o > 0; o >>= 1)
            contrib += __shfl_xor_sync(0xffffffffu, contrib, o);
        if (t == 0) out[b] = contrib + b3[bucket] + l1f;
    }
}

extern "C" void kernel_launch(void* const* d_in, const int* in_sizes, int n_in,
                              void* d_out, int out_size) {
    const float* us   = (const float*)d_in[0];
    const float* them = (const float*)d_in[1];
    const int*   widx = (const int*)  d_in[2];
    const float* wval = (const float*)d_in[3];
    const int*   bidx = (const int*)  d_in[4];
    const float* bval = (const float*)d_in[5];
    const int*   lsi  = (const int*)  d_in[6];
    const float* W_ft = (const float*)d_in[7];
    const float* b_ft = (const float*)d_in[8];
    const float* W1   = (const float*)d_in[9];
    const float* b1   = (const float*)d_in[10];
    const float* W2   = (const float*)d_in[11];
    const float* b2   = (const float*)d_in[12];
    const float* W3   = (const float*)d_in[13];
    const float* b3   = (const float*)d_in[14];
    float* out = (float*)d_out;

    const int B = in_sizes[0];

    prologue_kernel<<<CONV_BLOCKS + W1_BLOCKS, 256>>>(W_ft, W1);

    nnue_fused_kernel<<<B, 256>>>(us, them, widx, wval, bidx, bval, lsi,
                                  b_ft, b1, W2, b2, W3, b3, out);
}

// round 13
// speedup vs baseline: 2.0652x; 1.0062x over previous
#include <cuda_runtime.h>
#include <cuda_fp16.h>

// NNUE forward, fused. v7:
//  - prologue: W_ft fp32->fp16 (flat, 4-way ILP, streaming) + W1 transpose fp16
//  - main: one CTA per batch row; 8 CTAs/SM (regs<=32); gather LDG.128 with
//    wp/bp thread split; stages 2+3 merged (one less sync + SMEM pass)
//
// Inputs (metadata order):
//  0 us(B) 1 them(B) 2 white_indices(B*32 i32) 3 white_values(B*32)
//  4 black_indices 5 black_values 6 layer_stack_indices(B i32)
//  7 W_ft(22528*1024) 8 b_ft(1024) 9 W1(1024*144) 10 b1(144)
// 11 W2(30*288) 12 b2(288) 13 W3(32*9) 14 b3(9)

#define KIDX   32
#define L1DIM  1024
#define L2DIM  15
#define L3DIM  32
#define NBUCK  9
#define NF     22528
#define W1COLS (NBUCK * (L2DIM + 1))   // 144
#define W2COLS (NBUCK * L3DIM)         // 288
#define FSC    (127.0f / 128.0f)

#define N4      ((size_t)NF * L1DIM / 4)       // 5,767,168 Half4 elements
#define CHUNK   (N4 / 4)                        // 1,441,792
#define CONV_BLOCKS ((int)(CHUNK / 256))        // 5632
#define W1N     (NBUCK * 16 * L1DIM)            // 147,456
#define W1_BLOCKS ((W1N + 255) / 256)           // 576

struct __align__(8) Half4 { __half2 a, b; };

__device__ Half4 g_Wft16[N4];                   // 46 MB fp16 copy of W_ft
__device__ Half4 g_W1t16[W1N / 4];              // 288 KB fp16 [bucket][j][e]

static __device__ __forceinline__ float clamp01(float x) {
    return fminf(fmaxf(x, 0.0f), 1.0f);
}

static __device__ __forceinline__ Half4 cvt4(float4 v) {
    Half4 h;
    h.a = __floats2half2_rn(v.x, v.y);
    h.b = __floats2half2_rn(v.z, v.w);
    return h;
}

// ---------------- prologue: convert W_ft + transpose W1 ----------------
__global__ __launch_bounds__(256)
void prologue_kernel(const float* __restrict__ W_ft,
                     const float* __restrict__ W1) {
    if (blockIdx.x < CONV_BLOCKS) {
        const size_t g = (size_t)blockIdx.x * 256 + threadIdx.x;
        const float4* src = reinterpret_cast<const float4*>(W_ft);
        const float4 v0 = __ldcs(&src[g]);
        const float4 v1 = __ldcs(&src[g + CHUNK]);
        const float4 v2 = __ldcs(&src[g + 2 * CHUNK]);
        const float4 v3 = __ldcs(&src[g + 3 * CHUNK]);
        g_Wft16[g]             = cvt4(v0);
        g_Wft16[g + CHUNK]     = cvt4(v1);
        g_Wft16[g + 2 * CHUNK] = cvt4(v2);
        g_Wft16[g + 3 * CHUNK] = cvt4(v3);
    } else {
        const int i = (blockIdx.x - CONV_BLOCKS) * 256 + threadIdx.x;
        if (i < W1N) {
            const int e   = i & (L1DIM - 1);
            const int j   = (i >> 10) & 15;
            const int bkt = i >> 14;
            reinterpret_cast<__half*>(g_W1t16)[i] =
                __float2half_rn(W1[(size_t)e * W1COLS + bkt * 16 + j]);
        }
    }
}

// ---------------- main fused kernel ----------------
__global__ __launch_bounds__(256, 8)
void nnue_fused_kernel(
    const float* __restrict__ us,   const float* __restrict__ them,
    const int*   __restrict__ widx, const float* __restrict__ wval,
    const int*   __restrict__ bidx, const float* __restrict__ bval,
    const int*   __restrict__ lsi,
    const float* __restrict__ b_ft,
    const float* __restrict__ b1,
    const float* __restrict__ W2,   const float* __restrict__ b2,
    const float* __restrict__ W3,   const float* __restrict__ b3,
    float* __restrict__ out)
{
    const int b = blockIdx.x;
    const int t = threadIdx.x;
    const int warp = t >> 5;
    const int lane = t & 31;

    __shared__ unsigned s_off[2 * KIDX];   // byte offsets into g_Wft16
    __shared__ float    s_val[2 * KIDX];
    __shared__ float    s_a[L1DIM];        // raw wp
    __shared__ float    s_b[L1DIM];        // raw bp
    __shared__ float    s_l0p[L1DIM];      // pairwise-product activation
    __shared__ float    s_l1[16];          // l1c bucket slice

    // ---- stage 0: indices (as byte offsets) / values into SMEM ----
    if (t < KIDX) {
        s_off[t] = (unsigned)widx[b * KIDX + t] * (L1DIM * 2u);
        s_val[t] = wval[b * KIDX + t];
    } else if (t < 2 * KIDX) {
        s_off[t] = (unsigned)bidx[b * KIDX + (t - KIDX)] * (L1DIM * 2u);
        s_val[t] = bval[b * KIDX + (t - KIDX)];
    }
    __syncthreads();

    // ---- stage 1: gather/accumulate; threads 0-127: wp, 128-255: bp ----
    // each thread owns 8 columns: 8*tl .. 8*tl+7  (tl = t & 127)
    const int tl    = t & 127;
    const int kbase = (t < 128) ? 0 : KIDX;

    const float4* bft4 = reinterpret_cast<const float4*>(b_ft);
    float4 acc0 = bft4[2 * tl];
    float4 acc1 = bft4[2 * tl + 1];

    const char* wbase = reinterpret_cast<const char*>(g_Wft16);
    const unsigned lanebyte = (unsigned)tl * 16u;

    #pragma unroll 8
    for (int k = 0; k < KIDX; k++) {
        const unsigned off = s_off[kbase + k];
        const float    v   = s_val[kbase + k];
        const uint4 r = *reinterpret_cast<const uint4*>(wbase + off + lanebyte);
        const float2 p0 = __half22float2(*reinterpret_cast<const __half2*>(&r.x));
        const float2 p1 = __half22float2(*reinterpret_cast<const __half2*>(&r.y));
        const float2 p2 = __half22float2(*reinterpret_cast<const __half2*>(&r.z));
        const float2 p3 = __half22float2(*reinterpret_cast<const __half2*>(&r.w));
        acc0.x = fmaf(v, p0.x, acc0.x); acc0.y = fmaf(v, p0.y, acc0.y);
        acc0.z = fmaf(v, p1.x, acc0.z); acc0.w = fmaf(v, p1.y, acc0.w);
        acc1.x = fmaf(v, p2.x, acc1.x); acc1.y = fmaf(v, p2.y, acc1.y);
        acc1.z = fmaf(v, p3.x, acc1.z); acc1.w = fmaf(v, p3.y, acc1.w);
    }

    // stage raw wp into s_a (white threads), bp into s_b (black threads)
    {
        float4* dst = (t < 128) ? reinterpret_cast<float4*>(s_a)
                                : reinterpret_cast<float4*>(s_b);
        dst[2 * tl]     = acc0;
        dst[2 * tl + 1] = acc1;
    }
    __syncthreads();

    // ---- stage 2+3 merged: perspective combine + clamp + pairwise products ----
    const float u  = us[b];
    const float th = them[b];
    #pragma unroll
    for (int cix = t; cix < 512; cix += 256) {
        const float wpc  = s_a[cix],       bpc  = s_b[cix];
        const float wpc5 = s_a[cix + 512], bpc5 = s_b[cix + 512];
        const float A0 = clamp01(u * wpc  + th * bpc);
        const float A5 = clamp01(u * wpc5 + th * bpc5);
        const float B0 = clamp01(u * bpc  + th * wpc);
        const float B5 = clamp01(u * bpc5 + th * wpc5);
        s_l0p[cix]       = A0 * A5 * FSC;
        s_l0p[cix + 512] = B0 * B5 * FSC;
    }
    __syncthreads();

    // ---- stage 4: L1 — warp w computes outputs {2w, 2w+1} over 1024 elems ----
    const int bucket = lsi[b];
    {
        const Half4* wrow0 = g_W1t16
            + ((size_t)bucket * 16 + 2 * warp) * (L1DIM / 4);
        const Half4* wrow1 = wrow0 + (L1DIM / 4);
        const float4* x4 = reinterpret_cast<const float4*>(s_l0p);

        float v0 = 0.0f, v1 = 0.0f;
        #pragma unroll
        for (int i = 0; i < 8; i++) {
            const int e4 = i * 32 + lane;
            const float4 x  = x4[e4];
            const Half4  w0 = wrow0[e4];
            const Half4  w1 = wrow1[e4];
            const float2 l0 = __half22float2(w0.a);
            const float2 h0 = __half22float2(w0.b);
            const float2 l1 = __half22float2(w1.a);
            const float2 h1 = __half22float2(w1.b);
            v0 = fmaf(x.x, l0.x, v0); v0 = fmaf(x.y, l0.y, v0);
            v0 = fmaf(x.z, h0.x, v0); v0 = fmaf(x.w, h0.y, v0);
            v1 = fmaf(x.x, l1.x, v1); v1 = fmaf(x.y, l1.y, v1);
            v1 = fmaf(x.z, h1.x, v1); v1 = fmaf(x.w, h1.y, v1);
        }
        #pragma unroll
        for (int o = 16; o > 0; o >>= 1) {
            v0 += __shfl_xor_sync(0xffffffffu, v0, o);
            v1 += __shfl_xor_sync(0xffffffffu, v1, o);
        }
        if (lane == 0) {
            s_l1[2 * warp]     = v0 + b1[bucket * 16 + 2 * warp];
            s_l1[2 * warp + 1] = v1 + b1[bucket * 16 + 2 * warp + 1];
        }
    }
    __syncthreads();

    // ---- stage 5: L2 + L3 tail on warp 0 ----
    if (t < 32) {
        const float l1f = s_l1[15];          // pass-through term, NOT clipped
        float acc = b2[bucket * L3DIM + t];
        #pragma unroll
        for (int i = 0; i < L2DIM; i++) {
            const float x  = clamp01(s_l1[i]);
            const float wa = W2[(size_t)i * W2COLS + bucket * L3DIM + t];
            const float wb = W2[(size_t)(i + L2DIM) * W2COLS + bucket * L3DIM + t];
            acc = fmaf(x * x * FSC, wa, acc);
            acc = fmaf(x * FSC,     wb, acc);
        }
        const float l2x = clamp01(acc);
        float contrib = l2x * W3[t * NBUCK + bucket];
        #pragma unroll
        for (int o = 16; o > 0; o >>= 1)
            contrib += __shfl_xor_sync(0xffffffffu, contrib, o);
        if (t == 0) out[b] = contrib + b3[bucket] + l1f;
    }
}

extern "C" void kernel_launch(void* const* d_in, const int* in_sizes, int n_in,
                              void* d_out, int out_size) {
    const float* us   = (const float*)d_in[0];
    const float* them = (const float*)d_in[1];
    const int*   widx = (const int*)  d_in[2];
    const float* wval = (const float*)d_in[3];
    const int*   bidx = (const int*)  d_in[4];
    const float* bval = (const float*)d_in[5];
    const int*   lsi  = (const int*)  d_in[6];
    const float* W_ft = (const float*)d_in[7];
    const float* b_ft = (const float*)d_in[8];
    const float* W1   = (const float*)d_in[9];
    const float* b1   = (const float*)d_in[10];
    const float* W2   = (const float*)d_in[11];
    const float* b2   = (const float*)d_in[12];
    const float* W3   = (const float*)d_in[13];
    const float* b3   = (const float*)d_in[14];
    float* out = (float*)d_out;

    const int B = in_sizes[0];

    prologue_kernel<<<CONV_BLOCKS + W1_BLOCKS, 256>>>(W_ft, W1);

    nnue_fused_kernel<<<B, 256>>>(us, them, widx, wval, bidx, bval, lsi,
                                  b_ft, b1, W2, b2, W3, b3, out);
}